// round 3
// baseline (speedup 1.0000x reference)
#include <cuda_runtime.h>
#include <math.h>

#define Nn 2
#define Hh 8
#define Ss 1024
#define DHh 64
#define Dd 512
#define Pp 2047   // 2S-1

// Scratch (device global: no allocations allowed)
__device__ float g_R[Hh * Pp * DHh];      // r reshaped [h][p][d]

__device__ __forceinline__ unsigned f2tf(float x) {
    unsigned r;
    asm("cvt.rna.tf32.f32 %0, %1;" : "=r"(r) : "f"(x));
    return r;
}
__device__ __forceinline__ float tf32f(float x) { return __uint_as_float(f2tf(x)); }
__device__ __forceinline__ void mma_tf32(float c[4], unsigned a0, unsigned a1,
                                         unsigned a2, unsigned a3,
                                         unsigned b0, unsigned b1) {
    asm volatile(
        "mma.sync.aligned.m16n8k8.row.col.f32.tf32.tf32.f32 "
        "{%0,%1,%2,%3},{%4,%5,%6,%7},{%8,%9},{%0,%1,%2,%3};"
        : "+f"(c[0]), "+f"(c[1]), "+f"(c[2]), "+f"(c[3])
        : "r"(a0), "r"(a1), "r"(a2), "r"(a3), "r"(b0), "r"(b1));
}
__device__ __forceinline__ unsigned ldb(const float* p) { return __float_as_uint(*p); }

// ---------------------------------------------------------------------------
// Kernel 1: fused enc + r-projection, tf32 tensor cores.
// R[h][p][d] = sum_j ENC(p,j) * W[(h*64+d)][j].  grid (32 p-tiles, 8 heads).
// ---------------------------------------------------------------------------
__global__ void __launch_bounds__(256) rproj_mma_kernel(const float* __restrict__ W) {
    __shared__ float As[64 * 36];   // ENC tile [p][k], tf32
    __shared__ float Bsm[64 * 36];  // W   tile [c][k], tf32

    int tid = threadIdx.x;
    int warp = tid >> 5, lane = tid & 31;
    int g = lane >> 2, tg = lane & 3;
    int wm = (warp & 3) * 16;
    int wn = warp >> 2;

    int p0 = blockIdx.x * 64;
    int h = blockIdx.y;
    int c0 = h * 64;

    float acc[4][4] = {};
    const float coef = -9.210340371976184f / 512.0f;  // -ln(10000)/D

    for (int j0 = 0; j0 < Dd; j0 += 32) {
        __syncthreads();
        // enc on the fly: 1024 (sin,cos) pairs per tile
#pragma unroll
        for (int r = 0; r < 4; r++) {
            int q = tid + r * 256;
            int row = q >> 4, pj = q & 15;
            float pos = (float)(1023 - (p0 + row));
            float invf = __expf((float)(j0 + 2 * pj) * coef);
            float s, c;
            sincosf(pos * invf, &s, &c);
            float2 v; v.x = tf32f(s); v.y = tf32f(c);
            *(float2*)&As[row * 36 + 2 * pj] = v;
        }
#pragma unroll
        for (int r = 0; r < 2; r++) {
            int q2 = tid + r * 256;
            int row = q2 >> 3, qq = q2 & 7;
            float4 w = *(const float4*)&W[(size_t)(c0 + row) * Dd + j0 + 4 * qq];
            float4 o; o.x = tf32f(w.x); o.y = tf32f(w.y); o.z = tf32f(w.z); o.w = tf32f(w.w);
            *(float4*)&Bsm[row * 36 + 4 * qq] = o;
        }
        __syncthreads();
#pragma unroll
        for (int k0 = 0; k0 < 32; k0 += 8) {
            unsigned a0 = ldb(&As[(wm + g) * 36 + k0 + tg]);
            unsigned a1 = ldb(&As[(wm + g + 8) * 36 + k0 + tg]);
            unsigned a2 = ldb(&As[(wm + g) * 36 + k0 + tg + 4]);
            unsigned a3 = ldb(&As[(wm + g + 8) * 36 + k0 + tg + 4]);
#pragma unroll
            for (int nt = 0; nt < 4; nt++) {
                int n0 = wn * 32 + nt * 8;
                unsigned b0 = ldb(&Bsm[(n0 + g) * 36 + k0 + tg]);
                unsigned b1 = ldb(&Bsm[(n0 + g) * 36 + k0 + tg + 4]);
                mma_tf32(acc[nt], a0, a1, a2, a3, b0, b1);
            }
        }
    }
    int pA = p0 + wm + g, pB = pA + 8;
    float* Rh = g_R + (size_t)h * (Pp * DHh);
#pragma unroll
    for (int nt = 0; nt < 4; nt++) {
        int n0 = wn * 32 + nt * 8;
        if (pA < Pp)
            *(float2*)&Rh[(size_t)pA * DHh + n0 + 2 * tg] = make_float2(acc[nt][0], acc[nt][1]);
        if (pB < Pp)
            *(float2*)&Rh[(size_t)pB * DHh + n0 + 2 * tg] = make_float2(acc[nt][2], acc[nt][3]);
    }
}

// ---------------------------------------------------------------------------
// Kernel 2: fused causal flash attention, tf32 mma, sliding BD band,
// register-resident softmax. grid (8,16): block bx does qtiles {15-bx, bx}.
// ---------------------------------------------------------------------------
#define SQU 0                      // Qu [64][68]
#define SQV (SQU + 64*68)          // Qv
#define SKS (SQV + 64*68)          // Ks [kj][d]
#define SVS (SKS + 64*68)          // Vs [kj][d] [64][72]
#define SRS (SVS + 64*72)          // Rs ring: 2 x [64][68] (contig 128x68)
#define SSC (SRS + 2*64*68)        // P   [64][68]
#define SBS (SSC + 64*68)          // BD ring: 2 x [64][68]
#define SMM (SBS + 2*64*68)        // m [64]
#define SLL (SMM + 64)             // l [64]
#define SPM (SLL + 64)             // partial max [2][64]
#define SPS (SPM + 128)            // partial sum [2][64]
#define STOT (SPS + 128)

__global__ void __launch_bounds__(256) attn_kernel(
    const float* __restrict__ seqs, const float* __restrict__ keys,
    const float* __restrict__ values, const float* __restrict__ u_bias,
    const float* __restrict__ v_bias, float* __restrict__ out)
{
    extern __shared__ float sm[];
    float* Qu = sm + SQU;
    float* Qv = sm + SQV;
    float* Ks = sm + SKS;
    float* Vs = sm + SVS;
    float* Rs = sm + SRS;
    float* Sc = sm + SSC;
    float* Bs = sm + SBS;
    float* sM = sm + SMM;
    float* sL = sm + SLL;
    float* sPM = sm + SPM;
    float* sPS = sm + SPS;

    int tid = threadIdx.x;
    int warp = tid >> 5, lane = tid & 31;
    int g = lane >> 2, tg = lane & 3;
    int wm = (warp & 3) * 16;
    int wn = warp >> 2;
    int rA = wm + g, rB = wm + g + 8;

    int bx = blockIdx.x;
    int head = blockIdx.y;
    int n = head >> 3, h = head & 7;

    const float* sq = seqs   + ((size_t)(n * Hh + h) * Ss) * DHh;
    const float* kq = keys   + ((size_t)(n * Hh + h) * Ss) * DHh;
    const float* vq = values + ((size_t)(n * Hh + h) * Ss) * DHh;
    const float* Rh = g_R + (size_t)h * (Pp * DHh);

    int lrow = tid >> 4;   // row loader base
    int lq4  = tid & 15;   // float4 slot

    float4 ub4 = *(const float4*)&u_bias[h * DHh + lq4 * 4];
    float4 vb4 = *(const float4*)&v_bias[h * DHh + lq4 * 4];
    const float scale = 0.125f;

    for (int ph = 0; ph < 2; ph++) {
        int qt = (ph == 0) ? (15 - bx) : bx;
        int i0 = qt * 64;

        __syncthreads();   // prev phase fully consumed
#pragma unroll
        for (int r = 0; r < 4; r++) {
            int row = lrow + r * 16;
            float4 s4 = *(const float4*)&sq[(size_t)(i0 + row) * DHh + lq4 * 4];
            Qu[row * 68 + lq4 * 4 + 0] = tf32f(s4.x + ub4.x);
            Qu[row * 68 + lq4 * 4 + 1] = tf32f(s4.y + ub4.y);
            Qu[row * 68 + lq4 * 4 + 2] = tf32f(s4.z + ub4.z);
            Qu[row * 68 + lq4 * 4 + 3] = tf32f(s4.w + ub4.w);
            Qv[row * 68 + lq4 * 4 + 0] = tf32f(s4.x + vb4.x);
            Qv[row * 68 + lq4 * 4 + 1] = tf32f(s4.y + vb4.y);
            Qv[row * 68 + lq4 * 4 + 2] = tf32f(s4.z + vb4.z);
            Qv[row * 68 + lq4 * 4 + 3] = tf32f(s4.w + vb4.w);
        }
        if (tid < 64) { sM[tid] = -INFINITY; sL[tid] = 0.0f; }

        float O[4][4];
#pragma unroll
        for (int a = 0; a < 4; a++)
#pragma unroll
            for (int b = 0; b < 4; b++) O[a][b] = 0.0f;

        for (int kt = 0; kt <= qt; kt++) {
            int j0 = kt * 64;
            int pbase = (Ss - 1) - i0 + j0 - 63;
            int first = (kt == 0);
            int bufLow = kt & 1, bufHigh = bufLow ^ 1;

            __syncthreads();   // S1: prev-iter consumers done
#pragma unroll
            for (int r = 0; r < 4; r++) {
                int row = lrow + r * 16;
                float4 k4 = *(const float4*)&kq[(size_t)(j0 + row) * DHh + lq4 * 4];
                float4 v4 = *(const float4*)&vq[(size_t)(j0 + row) * DHh + lq4 * 4];
                Ks[row * 68 + lq4 * 4 + 0] = tf32f(k4.x);
                Ks[row * 68 + lq4 * 4 + 1] = tf32f(k4.y);
                Ks[row * 68 + lq4 * 4 + 2] = tf32f(k4.z);
                Ks[row * 68 + lq4 * 4 + 3] = tf32f(k4.w);
                Vs[row * 72 + lq4 * 4 + 0] = tf32f(v4.x);
                Vs[row * 72 + lq4 * 4 + 1] = tf32f(v4.y);
                Vs[row * 72 + lq4 * 4 + 2] = tf32f(v4.z);
                Vs[row * 72 + lq4 * 4 + 3] = tf32f(v4.w);
            }
            if (first) {
#pragma unroll
                for (int r = 0; r < 8; r++) {
                    int row = lrow + r * 16;   // band row 0..127, contiguous alias
                    float4 r4 = *(const float4*)&Rh[(size_t)(pbase + row) * DHh + lq4 * 4];
                    Rs[row * 68 + lq4 * 4 + 0] = tf32f(r4.x);
                    Rs[row * 68 + lq4 * 4 + 1] = tf32f(r4.y);
                    Rs[row * 68 + lq4 * 4 + 2] = tf32f(r4.z);
                    Rs[row * 68 + lq4 * 4 + 3] = tf32f(r4.w);
                }
            } else {
                float* Rdst = Rs + bufHigh * (64 * 68);
#pragma unroll
                for (int r = 0; r < 4; r++) {
                    int row = lrow + r * 16;   // new band rows 64..127
                    float4 r4 = *(const float4*)&Rh[(size_t)(pbase + 64 + row) * DHh + lq4 * 4];
                    Rdst[row * 68 + lq4 * 4 + 0] = tf32f(r4.x);
                    Rdst[row * 68 + lq4 * 4 + 1] = tf32f(r4.y);
                    Rdst[row * 68 + lq4 * 4 + 2] = tf32f(r4.z);
                    Rdst[row * 68 + lq4 * 4 + 3] = tf32f(r4.w);
                }
            }
            __syncthreads();   // S2: tiles ready

            // ---- AC = Qu @ K^T (regs) ----
            float cS[4][4];
#pragma unroll
            for (int t = 0; t < 4; t++)
#pragma unroll
                for (int e = 0; e < 4; e++) cS[t][e] = 0.0f;
#pragma unroll
            for (int k0 = 0; k0 < 64; k0 += 8) {
                unsigned a0 = ldb(&Qu[rA * 68 + k0 + tg]);
                unsigned a1 = ldb(&Qu[rB * 68 + k0 + tg]);
                unsigned a2 = ldb(&Qu[rA * 68 + k0 + tg + 4]);
                unsigned a3 = ldb(&Qu[rB * 68 + k0 + tg + 4]);
#pragma unroll
                for (int nt = 0; nt < 4; nt++) {
                    int n0 = wn * 32 + nt * 8;
                    unsigned b0 = ldb(&Ks[(n0 + g) * 68 + k0 + tg]);
                    unsigned b1 = ldb(&Ks[(n0 + g) * 68 + k0 + tg + 4]);
                    mma_tf32(cS[nt], a0, a1, a2, a3, b0, b1);
                }
            }

            // ---- BD: only new band columns (both halves on first iter) ----
            {
                int NT = first ? 8 : 4;
                float cB[8][4];
#pragma unroll
                for (int t = 0; t < 8; t++)
#pragma unroll
                    for (int e = 0; e < 4; e++) cB[t][e] = 0.0f;
#pragma unroll
                for (int k0 = 0; k0 < 64; k0 += 8) {
                    unsigned a0 = ldb(&Qv[rA * 68 + k0 + tg]);
                    unsigned a1 = ldb(&Qv[rB * 68 + k0 + tg]);
                    unsigned a2 = ldb(&Qv[rA * 68 + k0 + tg + 4]);
                    unsigned a3 = ldb(&Qv[rB * 68 + k0 + tg + 4]);
                    for (int nt = 0; nt < NT; nt++) {
                        // band row base within ring
                        int o0 = first ? (wn * 64 + nt * 8) : (64 + wn * 32 + nt * 8);
                        const float* Rb = first ? (Rs + o0 * 68)
                                                : (Rs + bufHigh * (64*68) + (o0 & 63) * 68);
                        unsigned b0 = ldb(&Rb[g * 68 + k0 + tg]);
                        unsigned b1 = ldb(&Rb[g * 68 + k0 + tg + 4]);
                        mma_tf32(cB[nt], a0, a1, a2, a3, b0, b1);
                    }
                }
                for (int nt = 0; nt < NT; nt++) {
                    int o0 = first ? (wn * 64 + nt * 8) : (64 + wn * 32 + nt * 8);
                    int bufI = first ? (o0 >> 6) : bufHigh;
                    float* Bd = Bs + bufI * (64 * 68) + (o0 & 63) + 2 * tg;
                    *(float2*)&Bd[rA * 68] = make_float2(cB[nt][0], cB[nt][1]);
                    *(float2*)&Bd[rB * 68] = make_float2(cB[nt][2], cB[nt][3]);
                }
            }
            __syncthreads();   // S3a: BD visible

            // ---- scores + partial row max (regs) ----
            float sv[4][4];
            float mA = -INFINITY, mB = -INFINITY;
            int diag = (kt == qt);
#pragma unroll
            for (int nt = 0; nt < 4; nt++) {
                int colbase = wn * 32 + nt * 8 + 2 * tg;
#pragma unroll
                for (int e = 0; e < 4; e++) {
                    int j = colbase + (e & 1);
                    int row = (e < 2) ? rA : rB;
                    int o = j - row + 63;
                    float bd = Bs[(bufLow ^ (o >> 6)) * (64 * 68) + row * 68 + (o & 63)];
                    float s = (cS[nt][e] + bd) * scale;
                    if (diag && j > row) s = -INFINITY;
                    sv[nt][e] = s;
                    if (e < 2) mA = fmaxf(mA, s); else mB = fmaxf(mB, s);
                }
            }
            mA = fmaxf(mA, __shfl_xor_sync(0xffffffffu, mA, 1));
            mA = fmaxf(mA, __shfl_xor_sync(0xffffffffu, mA, 2));
            mB = fmaxf(mB, __shfl_xor_sync(0xffffffffu, mB, 1));
            mB = fmaxf(mB, __shfl_xor_sync(0xffffffffu, mB, 2));
            if (tg == 0) { sPM[wn * 64 + rA] = mA; sPM[wn * 64 + rB] = mB; }
            __syncthreads();   // S3b: partial maxima visible

            float moldA = sM[rA], moldB = sM[rB];
            float mnA = fmaxf(moldA, fmaxf(sPM[rA], sPM[64 + rA]));
            float mnB = fmaxf(moldB, fmaxf(sPM[rB], sPM[64 + rB]));
            float corrA = __expf(moldA - mnA);
            float corrB = __expf(moldB - mnB);
            float sumA = 0.0f, sumB = 0.0f;
#pragma unroll
            for (int nt = 0; nt < 4; nt++) {
                int colbase = wn * 32 + nt * 8 + 2 * tg;
                float e0 = __expf(sv[nt][0] - mnA);
                float e1 = __expf(sv[nt][1] - mnA);
                float e2 = __expf(sv[nt][2] - mnB);
                float e3 = __expf(sv[nt][3] - mnB);
                sumA += e0 + e1; sumB += e2 + e3;
                *(float2*)&Sc[rA * 68 + colbase] = make_float2(tf32f(e0), tf32f(e1));
                *(float2*)&Sc[rB * 68 + colbase] = make_float2(tf32f(e2), tf32f(e3));
            }
            sumA += __shfl_xor_sync(0xffffffffu, sumA, 1);
            sumA += __shfl_xor_sync(0xffffffffu, sumA, 2);
            sumB += __shfl_xor_sync(0xffffffffu, sumB, 1);
            sumB += __shfl_xor_sync(0xffffffffu, sumB, 2);
            if (tg == 0) { sPS[wn * 64 + rA] = sumA; sPS[wn * 64 + rB] = sumB; }

            // rescale O (regs)
#pragma unroll
            for (int nt = 0; nt < 4; nt++) {
                O[nt][0] *= corrA; O[nt][1] *= corrA;
                O[nt][2] *= corrB; O[nt][3] *= corrB;
            }
            __syncthreads();   // S4: P & partial sums visible

            if (wn == 0 && tg == 0) {
                sL[rA] = sL[rA] * corrA + sPS[rA] + sPS[64 + rA];
                sL[rB] = sL[rB] * corrB + sPS[rB] + sPS[64 + rB];
                sM[rA] = mnA; sM[rB] = mnB;
            }

            // ---- O += P @ V ----
#pragma unroll
            for (int k0 = 0; k0 < 64; k0 += 8) {
                unsigned a0 = ldb(&Sc[rA * 68 + k0 + tg]);
                unsigned a1 = ldb(&Sc[rB * 68 + k0 + tg]);
                unsigned a2 = ldb(&Sc[rA * 68 + k0 + tg + 4]);
                unsigned a3 = ldb(&Sc[rB * 68 + k0 + tg + 4]);
#pragma unroll
                for (int nt = 0; nt < 4; nt++) {
                    int n0 = wn * 32 + nt * 8;
                    unsigned b0 = ldb(&Vs[(k0 + tg) * 72 + n0 + g]);
                    unsigned b1 = ldb(&Vs[(k0 + tg + 4) * 72 + n0 + g]);
                    mma_tf32(O[nt], a0, a1, a2, a3, b0, b1);
                }
            }
        }

        __syncthreads();   // sL final
        float invA = 1.0f / sL[rA];
        float invB = 1.0f / sL[rB];
        float* op = out + ((size_t)(n * Hh + h) * Ss + i0) * DHh;
#pragma unroll
        for (int nt = 0; nt < 4; nt++) {
            int n0 = wn * 32 + nt * 8;
            *(float2*)&op[(size_t)rA * DHh + n0 + 2 * tg] =
                make_float2(O[nt][0] * invA, O[nt][1] * invA);
            *(float2*)&op[(size_t)rB * DHh + n0 + 2 * tg] =
                make_float2(O[nt][2] * invB, O[nt][3] * invB);
        }
    }
}

// ---------------------------------------------------------------------------
extern "C" void kernel_launch(void* const* d_in, const int* in_sizes, int n_in,
                              void* d_out, int out_size) {
    const float* seqs   = (const float*)d_in[0];
    const float* keys   = (const float*)d_in[1];
    const float* values = (const float*)d_in[2];
    const float* u_bias = (const float*)d_in[3];
    const float* v_bias = (const float*)d_in[4];
    const float* rproj  = (const float*)d_in[5];
    (void)in_sizes; (void)n_in; (void)out_size;

    const int smem_bytes = STOT * sizeof(float);
    cudaFuncSetAttribute(attn_kernel, cudaFuncAttributeMaxDynamicSharedMemorySize,
                         smem_bytes);

    rproj_mma_kernel<<<dim3(32, 8), 256>>>(rproj);
    attn_kernel<<<dim3(8, 16), 256, smem_bytes>>>(seqs, keys, values,
                                                  u_bias, v_bias,
                                                  (float*)d_out);
}

// round 4
// speedup vs baseline: 1.4348x; 1.4348x over previous
#include <cuda_runtime.h>
#include <math.h>

#define Nn 2
#define Hh 8
#define Ss 1024
#define DHh 64
#define Dd 512
#define Pp 2047   // 2S-1

__device__ float g_R[Hh * Pp * DHh];      // r reshaped [h][p][d]

__device__ __forceinline__ unsigned f2tf(float x) {
    unsigned r;
    asm("cvt.rna.tf32.f32 %0, %1;" : "=r"(r) : "f"(x));
    return r;
}
__device__ __forceinline__ float tf32f(float x) { return __uint_as_float(f2tf(x)); }
__device__ __forceinline__ void mma_tf32(float c[4], unsigned a0, unsigned a1,
                                         unsigned a2, unsigned a3,
                                         unsigned b0, unsigned b1) {
    asm volatile(
        "mma.sync.aligned.m16n8k8.row.col.f32.tf32.tf32.f32 "
        "{%0,%1,%2,%3},{%4,%5,%6,%7},{%8,%9},{%0,%1,%2,%3};"
        : "+f"(c[0]), "+f"(c[1]), "+f"(c[2]), "+f"(c[3])
        : "r"(a0), "r"(a1), "r"(a2), "r"(a3), "r"(b0), "r"(b1));
}
__device__ __forceinline__ unsigned ldb(const float* p) { return __float_as_uint(*p); }

// ---------------------------------------------------------------------------
// Kernel 1: fused enc + r-projection, tf32 tensor cores.
// ---------------------------------------------------------------------------
__global__ void __launch_bounds__(256) rproj_mma_kernel(const float* __restrict__ W) {
    __shared__ float As[64 * 36];
    __shared__ float Bsm[64 * 36];

    int tid = threadIdx.x;
    int warp = tid >> 5, lane = tid & 31;
    int g = lane >> 2, tg = lane & 3;
    int wm = (warp & 3) * 16;
    int wn = warp >> 2;

    int p0 = blockIdx.x * 64;
    int h = blockIdx.y;
    int c0 = h * 64;

    float acc[4][4] = {};
    const float coef = -9.210340371976184f / 512.0f;

    for (int j0 = 0; j0 < Dd; j0 += 32) {
        __syncthreads();
#pragma unroll
        for (int r = 0; r < 4; r++) {
            int q = tid + r * 256;
            int row = q >> 4, pj = q & 15;
            float pos = (float)(1023 - (p0 + row));
            float invf = __expf((float)(j0 + 2 * pj) * coef);
            float s, c;
            sincosf(pos * invf, &s, &c);
            float2 v; v.x = tf32f(s); v.y = tf32f(c);
            *(float2*)&As[row * 36 + 2 * pj] = v;
        }
#pragma unroll
        for (int r = 0; r < 2; r++) {
            int q2 = tid + r * 256;
            int row = q2 >> 3, qq = q2 & 7;
            float4 w = *(const float4*)&W[(size_t)(c0 + row) * Dd + j0 + 4 * qq];
            float4 o; o.x = tf32f(w.x); o.y = tf32f(w.y); o.z = tf32f(w.z); o.w = tf32f(w.w);
            *(float4*)&Bsm[row * 36 + 4 * qq] = o;
        }
        __syncthreads();
#pragma unroll
        for (int k0 = 0; k0 < 32; k0 += 8) {
            unsigned a0 = ldb(&As[(wm + g) * 36 + k0 + tg]);
            unsigned a1 = ldb(&As[(wm + g + 8) * 36 + k0 + tg]);
            unsigned a2 = ldb(&As[(wm + g) * 36 + k0 + tg + 4]);
            unsigned a3 = ldb(&As[(wm + g + 8) * 36 + k0 + tg + 4]);
#pragma unroll
            for (int nt = 0; nt < 4; nt++) {
                int n0 = wn * 32 + nt * 8;
                unsigned b0 = ldb(&Bsm[(n0 + g) * 36 + k0 + tg]);
                unsigned b1 = ldb(&Bsm[(n0 + g) * 36 + k0 + tg + 4]);
                mma_tf32(acc[nt], a0, a1, a2, a3, b0, b1);
            }
        }
    }
    int pA = p0 + wm + g, pB = pA + 8;
    float* Rh = g_R + (size_t)h * (Pp * DHh);
#pragma unroll
    for (int nt = 0; nt < 4; nt++) {
        int n0 = wn * 32 + nt * 8;
        if (pA < Pp)
            *(float2*)&Rh[(size_t)pA * DHh + n0 + 2 * tg] = make_float2(acc[nt][0], acc[nt][1]);
        if (pB < Pp)
            *(float2*)&Rh[(size_t)pB * DHh + n0 + 2 * tg] = make_float2(acc[nt][2], acc[nt][3]);
    }
}

// ---------------------------------------------------------------------------
// Kernel 2: fused causal flash attention, tf32 mma, sliding BD band,
// 512 threads (16 warps, 4-way n-split). grid (8,16), qtiles {15-bx, bx}.
// ---------------------------------------------------------------------------
#define SQU 0
#define SQV (SQU + 64*68)
#define SKS (SQV + 64*68)
#define SVS (SKS + 64*68)          // [64][72]
#define SRS (SVS + 64*72)          // ring 2 x [64][68]
#define SSC (SRS + 2*64*68)        // P [64][68]
#define SBS (SSC + 64*68)          // ring 2 x [64][68]
#define SMM (SBS + 2*64*68)        // m [64]
#define SLL (SMM + 64)             // l [64]
#define SPM (SLL + 64)             // partial max [4][64]
#define SPS (SPM + 256)            // partial sum [4][64]
#define STOT (SPS + 256)

__global__ void __launch_bounds__(512) attn_kernel(
    const float* __restrict__ seqs, const float* __restrict__ keys,
    const float* __restrict__ values, const float* __restrict__ u_bias,
    const float* __restrict__ v_bias, float* __restrict__ out)
{
    extern __shared__ float sm[];
    float* Qu = sm + SQU;
    float* Qv = sm + SQV;
    float* Ks = sm + SKS;
    float* Vs = sm + SVS;
    float* Rs = sm + SRS;
    float* Sc = sm + SSC;
    float* Bs = sm + SBS;
    float* sM = sm + SMM;
    float* sL = sm + SLL;
    float* sPM = sm + SPM;
    float* sPS = sm + SPS;

    int tid = threadIdx.x;
    int warp = tid >> 5, lane = tid & 31;
    int g = lane >> 2, tg = lane & 3;
    int wm = (warp & 3) * 16;
    int wn = warp >> 2;           // 0..3: 16-col slice
    int rA = wm + g, rB = wm + g + 8;

    int bx = blockIdx.x;
    int head = blockIdx.y;
    int n = head >> 3, h = head & 7;

    const float* sq = seqs   + ((size_t)(n * Hh + h) * Ss) * DHh;
    const float* kq = keys   + ((size_t)(n * Hh + h) * Ss) * DHh;
    const float* vq = values + ((size_t)(n * Hh + h) * Ss) * DHh;
    const float* Rh = g_R + (size_t)h * (Pp * DHh);

    int lrow = tid >> 4;   // 0..31
    int lq4  = tid & 15;

    float4 ub4 = *(const float4*)&u_bias[h * DHh + lq4 * 4];
    float4 vb4 = *(const float4*)&v_bias[h * DHh + lq4 * 4];
    const float scale = 0.125f;

    for (int ph = 0; ph < 2; ph++) {
        int qt = (ph == 0) ? (15 - bx) : bx;
        int i0 = qt * 64;

        __syncthreads();
#pragma unroll
        for (int r = 0; r < 2; r++) {
            int row = lrow + r * 32;
            float4 s4 = *(const float4*)&sq[(size_t)(i0 + row) * DHh + lq4 * 4];
            Qu[row * 68 + lq4 * 4 + 0] = tf32f(s4.x + ub4.x);
            Qu[row * 68 + lq4 * 4 + 1] = tf32f(s4.y + ub4.y);
            Qu[row * 68 + lq4 * 4 + 2] = tf32f(s4.z + ub4.z);
            Qu[row * 68 + lq4 * 4 + 3] = tf32f(s4.w + ub4.w);
            Qv[row * 68 + lq4 * 4 + 0] = tf32f(s4.x + vb4.x);
            Qv[row * 68 + lq4 * 4 + 1] = tf32f(s4.y + vb4.y);
            Qv[row * 68 + lq4 * 4 + 2] = tf32f(s4.z + vb4.z);
            Qv[row * 68 + lq4 * 4 + 3] = tf32f(s4.w + vb4.w);
        }
        if (tid < 64) { sM[tid] = -INFINITY; sL[tid] = 0.0f; }

        float O[2][4];
#pragma unroll
        for (int a = 0; a < 2; a++)
#pragma unroll
            for (int b = 0; b < 4; b++) O[a][b] = 0.0f;

        for (int kt = 0; kt <= qt; kt++) {
            int j0 = kt * 64;
            int pbase = (Ss - 1) - i0 + j0 - 63;
            int bufLow = kt & 1, bufHigh = bufLow ^ 1;

            __syncthreads();   // S1
#pragma unroll
            for (int r = 0; r < 2; r++) {
                int row = lrow + r * 32;
                float4 k4 = *(const float4*)&kq[(size_t)(j0 + row) * DHh + lq4 * 4];
                float4 v4 = *(const float4*)&vq[(size_t)(j0 + row) * DHh + lq4 * 4];
                Ks[row * 68 + lq4 * 4 + 0] = tf32f(k4.x);
                Ks[row * 68 + lq4 * 4 + 1] = tf32f(k4.y);
                Ks[row * 68 + lq4 * 4 + 2] = tf32f(k4.z);
                Ks[row * 68 + lq4 * 4 + 3] = tf32f(k4.w);
                Vs[row * 72 + lq4 * 4 + 0] = tf32f(v4.x);
                Vs[row * 72 + lq4 * 4 + 1] = tf32f(v4.y);
                Vs[row * 72 + lq4 * 4 + 2] = tf32f(v4.z);
                Vs[row * 72 + lq4 * 4 + 3] = tf32f(v4.w);
            }
            if (kt == 0) {
#pragma unroll
                for (int r = 0; r < 4; r++) {
                    int row = lrow + r * 32;   // 0..127 contiguous over ring
                    float4 r4 = *(const float4*)&Rh[(size_t)(pbase + row) * DHh + lq4 * 4];
                    Rs[row * 68 + lq4 * 4 + 0] = tf32f(r4.x);
                    Rs[row * 68 + lq4 * 4 + 1] = tf32f(r4.y);
                    Rs[row * 68 + lq4 * 4 + 2] = tf32f(r4.z);
                    Rs[row * 68 + lq4 * 4 + 3] = tf32f(r4.w);
                }
            } else {
                float* Rdst = Rs + bufHigh * (64 * 68);
#pragma unroll
                for (int r = 0; r < 2; r++) {
                    int row = lrow + r * 32;
                    float4 r4 = *(const float4*)&Rh[(size_t)(pbase + 64 + row) * DHh + lq4 * 4];
                    Rdst[row * 68 + lq4 * 4 + 0] = tf32f(r4.x);
                    Rdst[row * 68 + lq4 * 4 + 1] = tf32f(r4.y);
                    Rdst[row * 68 + lq4 * 4 + 2] = tf32f(r4.z);
                    Rdst[row * 68 + lq4 * 4 + 3] = tf32f(r4.w);
                }
            }
            __syncthreads();   // S2

            // ---- AC = Qu @ K^T : warp -> rows wm..+15, cols wn*16..+15 ----
            float cS[2][4];
#pragma unroll
            for (int t = 0; t < 2; t++)
#pragma unroll
                for (int e = 0; e < 4; e++) cS[t][e] = 0.0f;
#pragma unroll
            for (int k0 = 0; k0 < 64; k0 += 8) {
                unsigned a0 = ldb(&Qu[rA * 68 + k0 + tg]);
                unsigned a1 = ldb(&Qu[rB * 68 + k0 + tg]);
                unsigned a2 = ldb(&Qu[rA * 68 + k0 + tg + 4]);
                unsigned a3 = ldb(&Qu[rB * 68 + k0 + tg + 4]);
#pragma unroll
                for (int nt = 0; nt < 2; nt++) {
                    int n0 = wn * 16 + nt * 8;
                    unsigned b0 = ldb(&Ks[(n0 + g) * 68 + k0 + tg]);
                    unsigned b1 = ldb(&Ks[(n0 + g) * 68 + k0 + tg + 4]);
                    mma_tf32(cS[nt], a0, a1, a2, a3, b0, b1);
                }
            }

            // ---- BD (fully unrolled, compile-time trip counts) ----
            if (kt == 0) {
                float cB[4][4];
#pragma unroll
                for (int t = 0; t < 4; t++)
#pragma unroll
                    for (int e = 0; e < 4; e++) cB[t][e] = 0.0f;
#pragma unroll
                for (int k0 = 0; k0 < 64; k0 += 8) {
                    unsigned a0 = ldb(&Qv[rA * 68 + k0 + tg]);
                    unsigned a1 = ldb(&Qv[rB * 68 + k0 + tg]);
                    unsigned a2 = ldb(&Qv[rA * 68 + k0 + tg + 4]);
                    unsigned a3 = ldb(&Qv[rB * 68 + k0 + tg + 4]);
#pragma unroll
                    for (int nt = 0; nt < 4; nt++) {
                        int o0 = wn * 32 + nt * 8;     // band row 0..127
                        unsigned b0 = ldb(&Rs[(o0 + g) * 68 + k0 + tg]);
                        unsigned b1 = ldb(&Rs[(o0 + g) * 68 + k0 + tg + 4]);
                        mma_tf32(cB[nt], a0, a1, a2, a3, b0, b1);
                    }
                }
#pragma unroll
                for (int nt = 0; nt < 4; nt++) {
                    int o0 = wn * 32 + nt * 8;
                    float* Bd = Bs + (o0 >> 6) * (64 * 68) + (o0 & 63) + 2 * tg;
                    *(float2*)&Bd[rA * 68] = make_float2(cB[nt][0], cB[nt][1]);
                    *(float2*)&Bd[rB * 68] = make_float2(cB[nt][2], cB[nt][3]);
                }
            } else {
                float cB[2][4];
#pragma unroll
                for (int t = 0; t < 2; t++)
#pragma unroll
                    for (int e = 0; e < 4; e++) cB[t][e] = 0.0f;
                const float* Rb = Rs + bufHigh * (64 * 68);
#pragma unroll
                for (int k0 = 0; k0 < 64; k0 += 8) {
                    unsigned a0 = ldb(&Qv[rA * 68 + k0 + tg]);
                    unsigned a1 = ldb(&Qv[rB * 68 + k0 + tg]);
                    unsigned a2 = ldb(&Qv[rA * 68 + k0 + tg + 4]);
                    unsigned a3 = ldb(&Qv[rB * 68 + k0 + tg + 4]);
#pragma unroll
                    for (int nt = 0; nt < 2; nt++) {
                        int r0 = wn * 16 + nt * 8;     // row in new buffer
                        unsigned b0 = ldb(&Rb[(r0 + g) * 68 + k0 + tg]);
                        unsigned b1 = ldb(&Rb[(r0 + g) * 68 + k0 + tg + 4]);
                        mma_tf32(cB[nt], a0, a1, a2, a3, b0, b1);
                    }
                }
                float* Bd0 = Bs + bufHigh * (64 * 68);
#pragma unroll
                for (int nt = 0; nt < 2; nt++) {
                    int r0 = wn * 16 + nt * 8;
                    float* Bd = Bd0 + r0 + 2 * tg;
                    *(float2*)&Bd[rA * 68] = make_float2(cB[nt][0], cB[nt][1]);
                    *(float2*)&Bd[rB * 68] = make_float2(cB[nt][2], cB[nt][3]);
                }
            }
            __syncthreads();   // S3a

            // ---- scores + partial max ----
            float sv[2][4];
            float mA = -INFINITY, mB = -INFINITY;
            int diag = (kt == qt);
#pragma unroll
            for (int nt = 0; nt < 2; nt++) {
                int colbase = wn * 16 + nt * 8 + 2 * tg;
#pragma unroll
                for (int e = 0; e < 4; e++) {
                    int j = colbase + (e & 1);
                    int row = (e < 2) ? rA : rB;
                    int o = j - row + 63;
                    float bd = Bs[(bufLow ^ (o >> 6)) * (64 * 68) + row * 68 + (o & 63)];
                    float s = (cS[nt][e] + bd) * scale;
                    if (diag && j > row) s = -INFINITY;
                    sv[nt][e] = s;
                    if (e < 2) mA = fmaxf(mA, s); else mB = fmaxf(mB, s);
                }
            }
            mA = fmaxf(mA, __shfl_xor_sync(0xffffffffu, mA, 1));
            mA = fmaxf(mA, __shfl_xor_sync(0xffffffffu, mA, 2));
            mB = fmaxf(mB, __shfl_xor_sync(0xffffffffu, mB, 1));
            mB = fmaxf(mB, __shfl_xor_sync(0xffffffffu, mB, 2));
            if (tg == 0) { sPM[wn * 64 + rA] = mA; sPM[wn * 64 + rB] = mB; }
            __syncthreads();   // S3b

            float moldA = sM[rA], moldB = sM[rB];
            float mnA = fmaxf(fmaxf(moldA, fmaxf(sPM[rA], sPM[64 + rA])),
                              fmaxf(sPM[128 + rA], sPM[192 + rA]));
            float mnB = fmaxf(fmaxf(moldB, fmaxf(sPM[rB], sPM[64 + rB])),
                              fmaxf(sPM[128 + rB], sPM[192 + rB]));
            float corrA = __expf(moldA - mnA);
            float corrB = __expf(moldB - mnB);
            float sumA = 0.0f, sumB = 0.0f;
#pragma unroll
            for (int nt = 0; nt < 2; nt++) {
                int colbase = wn * 16 + nt * 8 + 2 * tg;
                float e0 = __expf(sv[nt][0] - mnA);
                float e1 = __expf(sv[nt][1] - mnA);
                float e2 = __expf(sv[nt][2] - mnB);
                float e3 = __expf(sv[nt][3] - mnB);
                sumA += e0 + e1; sumB += e2 + e3;
                *(float2*)&Sc[rA * 68 + colbase] = make_float2(tf32f(e0), tf32f(e1));
                *(float2*)&Sc[rB * 68 + colbase] = make_float2(tf32f(e2), tf32f(e3));
            }
            sumA += __shfl_xor_sync(0xffffffffu, sumA, 1);
            sumA += __shfl_xor_sync(0xffffffffu, sumA, 2);
            sumB += __shfl_xor_sync(0xffffffffu, sumB, 1);
            sumB += __shfl_xor_sync(0xffffffffu, sumB, 2);
            if (tg == 0) { sPS[wn * 64 + rA] = sumA; sPS[wn * 64 + rB] = sumB; }

#pragma unroll
            for (int nt = 0; nt < 2; nt++) {
                O[nt][0] *= corrA; O[nt][1] *= corrA;
                O[nt][2] *= corrB; O[nt][3] *= corrB;
            }
            __syncthreads();   // S4

            if (wn == 0 && tg == 0) {
                sL[rA] = sL[rA] * corrA + (sPS[rA] + sPS[64 + rA]) + (sPS[128 + rA] + sPS[192 + rA]);
                sL[rB] = sL[rB] * corrB + (sPS[rB] + sPS[64 + rB]) + (sPS[128 + rB] + sPS[192 + rB]);
                sM[rA] = mnA; sM[rB] = mnB;
            }

            // ---- O += P @ V ----
#pragma unroll
            for (int k0 = 0; k0 < 64; k0 += 8) {
                unsigned a0 = ldb(&Sc[rA * 68 + k0 + tg]);
                unsigned a1 = ldb(&Sc[rB * 68 + k0 + tg]);
                unsigned a2 = ldb(&Sc[rA * 68 + k0 + tg + 4]);
                unsigned a3 = ldb(&Sc[rB * 68 + k0 + tg + 4]);
#pragma unroll
                for (int nt = 0; nt < 2; nt++) {
                    int n0 = wn * 16 + nt * 8;
                    unsigned b0 = ldb(&Vs[(k0 + tg) * 72 + n0 + g]);
                    unsigned b1 = ldb(&Vs[(k0 + tg + 4) * 72 + n0 + g]);
                    mma_tf32(O[nt], a0, a1, a2, a3, b0, b1);
                }
            }
        }

        __syncthreads();
        float invA = 1.0f / sL[rA];
        float invB = 1.0f / sL[rB];
        float* op = out + ((size_t)(n * Hh + h) * Ss + i0) * DHh;
#pragma unroll
        for (int nt = 0; nt < 2; nt++) {
            int n0 = wn * 16 + nt * 8;
            *(float2*)&op[(size_t)rA * DHh + n0 + 2 * tg] =
                make_float2(O[nt][0] * invA, O[nt][1] * invA);
            *(float2*)&op[(size_t)rB * DHh + n0 + 2 * tg] =
                make_float2(O[nt][2] * invB, O[nt][3] * invB);
        }
    }
}

// ---------------------------------------------------------------------------
extern "C" void kernel_launch(void* const* d_in, const int* in_sizes, int n_in,
                              void* d_out, int out_size) {
    const float* seqs   = (const float*)d_in[0];
    const float* keys   = (const float*)d_in[1];
    const float* values = (const float*)d_in[2];
    const float* u_bias = (const float*)d_in[3];
    const float* v_bias = (const float*)d_in[4];
    const float* rproj  = (const float*)d_in[5];
    (void)in_sizes; (void)n_in; (void)out_size;

    const int smem_bytes = STOT * sizeof(float);
    cudaFuncSetAttribute(attn_kernel, cudaFuncAttributeMaxDynamicSharedMemorySize,
                         smem_bytes);

    rproj_mma_kernel<<<dim3(32, 8), 256>>>(rproj);
    attn_kernel<<<dim3(8, 16), 512, smem_bytes>>>(seqs, keys, values,
                                                  u_bias, v_bias,
                                                  (float*)d_out);
}